// round 1
// baseline (speedup 1.0000x reference)
#include <cuda_runtime.h>
#include <cstdint>

// Problem constants
#define AN 3
#define SSZ 32
#define HH 128
#define WW 128
#define KK (SSZ*HH*WW)        // 524288 spatial positions
#define NN (KK*AN)            // 1572864 total anchors
#define PRE 2000
#define POST 300
#define WORDS 32              // 2048 bits >= PRE
#define CAP 4096
#define NMS_T 0.7f

// ---------------- device state ----------------
__device__ unsigned int g_hist1[65536];
__device__ unsigned int g_hist2[65536];
__device__ unsigned int g_hiBin;
__device__ unsigned int g_need2;
__device__ unsigned int g_T;
__device__ int          g_cand_count;
__device__ unsigned long long g_cand[CAP];

__device__ int   g_order[PRE];
__device__ float g_score[PRE];
__device__ float g_bx1[PRE], g_by1[PRE], g_bz1[PRE];
__device__ float g_bx2[PRE], g_by2[PRE], g_bz2[PRE];
__device__ float g_volv[PRE];
__device__ int   g_valid[PRE];
__device__ unsigned long long g_mask[PRE*WORDS];
__device__ unsigned long long g_remv[WORDS];

// ---------------- kernels ----------------
__global__ void init_k() {
    int t = blockIdx.x*blockDim.x + threadIdx.x;
    int stride = gridDim.x*blockDim.x;
    for (int o = t; o < 65536; o += stride) { g_hist1[o] = 0u; g_hist2[o] = 0u; }
    if (t == 0) g_cand_count = 0;
}

__global__ void hist1_k(const float* __restrict__ sc) {
    int stride = gridDim.x*blockDim.x;
    for (int t = blockIdx.x*blockDim.x + threadIdx.x; t < NN; t += stride) {
        unsigned b = __float_as_uint(sc[t]);
        atomicAdd(&g_hist1[b >> 16], 1u);
    }
}

__global__ void resolve1_k() {
    __shared__ unsigned cs[1024];
    __shared__ unsigned ss[1024];
    int t = threadIdx.x;
    unsigned s = 0;
    #pragma unroll 8
    for (int m = 0; m < 64; ++m) s += g_hist1[t*64 + m];
    cs[t] = s;
    int r = 1023 - t;           // reversed index: r grows downward in bin value
    ss[r] = s;
    __syncthreads();
    for (int off = 1; off < 1024; off <<= 1) {
        unsigned v = (r >= off) ? ss[r-off] : 0u;
        __syncthreads();
        ss[r] += v;
        __syncthreads();
    }
    unsigned need = PRE;
    unsigned incl = ss[r];              // sum over chunks >= t
    unsigned above = incl - cs[t];      // sum over chunks  > t
    if (above < need && need <= incl) {
        unsigned c = above;
        for (int m = 63; m >= 0; --m) {
            unsigned h = g_hist1[t*64 + m];
            if (c + h >= need) { g_hiBin = (unsigned)(t*64 + m); g_need2 = need - c; break; }
            c += h;
        }
    }
}

__global__ void hist2_k(const float* __restrict__ sc) {
    unsigned hi = g_hiBin;
    int stride = gridDim.x*blockDim.x;
    for (int t = blockIdx.x*blockDim.x + threadIdx.x; t < NN; t += stride) {
        unsigned b = __float_as_uint(sc[t]);
        if ((b >> 16) == hi) atomicAdd(&g_hist2[b & 0xFFFFu], 1u);
    }
}

__global__ void resolve2_k() {
    __shared__ unsigned cs[1024];
    __shared__ unsigned ss[1024];
    int t = threadIdx.x;
    unsigned s = 0;
    #pragma unroll 8
    for (int m = 0; m < 64; ++m) s += g_hist2[t*64 + m];
    cs[t] = s;
    int r = 1023 - t;
    ss[r] = s;
    __syncthreads();
    for (int off = 1; off < 1024; off <<= 1) {
        unsigned v = (r >= off) ? ss[r-off] : 0u;
        __syncthreads();
        ss[r] += v;
        __syncthreads();
    }
    unsigned need = g_need2;
    unsigned incl = ss[r];
    unsigned above = incl - cs[t];
    if (above < need && need <= incl) {
        unsigned c = above;
        for (int m = 63; m >= 0; --m) {
            unsigned h = g_hist2[t*64 + m];
            if (c + h >= need) { g_T = (g_hiBin << 16) | (unsigned)(t*64 + m); break; }
            c += h;
        }
    }
}

__global__ void compact_k(const float* __restrict__ sc) {
    unsigned T = g_T;
    int stride = gridDim.x*blockDim.x;
    for (int t = blockIdx.x*blockDim.x + threadIdx.x; t < NN; t += stride) {
        unsigned b = __float_as_uint(sc[t]);
        if (b >= T) {
            int a = t / KK;
            int p = t - a*KK;
            unsigned i = (unsigned)(p*3 + a);
            int pos = atomicAdd(&g_cand_count, 1);
            if (pos < CAP)
                g_cand[pos] = ((unsigned long long)b << 32) |
                              (unsigned long long)(0xFFFFFFFFu - i);
        }
    }
}

__global__ void sort_k() {
    __shared__ unsigned long long sk[CAP];
    int t = threadIdx.x;
    int cnt = g_cand_count; if (cnt > CAP) cnt = CAP;
    for (int idx = t; idx < CAP; idx += 1024) sk[idx] = (idx < cnt) ? g_cand[idx] : 0ull;
    __syncthreads();
    for (int k = 2; k <= CAP; k <<= 1) {
        for (int j = k >> 1; j > 0; j >>= 1) {
            for (int idx = t; idx < CAP; idx += 1024) {
                int l = idx ^ j;
                if (l > idx) {
                    bool desc = ((idx & k) == 0);
                    unsigned long long a = sk[idx], b = sk[l];
                    bool sw = desc ? (a < b) : (a > b);
                    if (sw) { sk[idx] = b; sk[l] = a; }
                }
            }
            __syncthreads();
        }
    }
    for (int r = t; r < PRE; r += 1024) {
        unsigned long long key = sk[r];
        g_order[r] = (int)(0xFFFFFFFFu - (unsigned)(key & 0xFFFFFFFFull));
        g_score[r] = __uint_as_float((unsigned)(key >> 32));
    }
}

__global__ void transform_k(const float* __restrict__ deltas,
                            const float* __restrict__ ii,
                            const float* __restrict__ anc) {
    int r = blockIdx.x*blockDim.x + threadIdx.x;
    if (r >= PRE) return;
    int i = g_order[r];
    int a = i % 3;
    int p = i / 3;
    int w = p % WW;
    int h = (p / WW) % HH;
    int s = p / (WW*HH);
    float shx = 4.0f * (float)w, shy = 4.0f * (float)h, shz = 4.0f * (float)s;
    float x1a = __fadd_rn(shx, anc[a*6+0]);
    float y1a = __fadd_rn(shy, anc[a*6+1]);
    float z1a = __fadd_rn(shz, anc[a*6+2]);
    float x2a = __fadd_rn(shx, anc[a*6+3]);
    float y2a = __fadd_rn(shy, anc[a*6+4]);
    float z2a = __fadd_rn(shz, anc[a*6+5]);
    float ww_ = __fadd_rn(__fsub_rn(x2a, x1a), 1.0f);
    float hh_ = __fadd_rn(__fsub_rn(y2a, y1a), 1.0f);
    float dd_ = __fadd_rn(__fsub_rn(z2a, z1a), 1.0f);
    float cx = __fadd_rn(x1a, __fmul_rn(0.5f, ww_));
    float cy = __fadd_rn(y1a, __fmul_rn(0.5f, hh_));
    float cz = __fadd_rn(z1a, __fmul_rn(0.5f, dd_));
    const float* dp = deltas + p;
    float dx = dp[(6*a+0)*KK];
    float dy = dp[(6*a+1)*KK];
    float dz = dp[(6*a+2)*KK];
    float dw = dp[(6*a+3)*KK];
    float dh = dp[(6*a+4)*KK];
    float dd = dp[(6*a+5)*KK];
    float pcx = __fadd_rn(__fmul_rn(dx, ww_), cx);
    float pcy = __fadd_rn(__fmul_rn(dy, hh_), cy);
    float pcz = __fadd_rn(__fmul_rn(dz, dd_), cz);
    float pw = __fmul_rn(expf(dw), ww_);
    float ph = __fmul_rn(expf(dh), hh_);
    float pd = __fmul_rn(expf(dd), dd_);
    float slices = ii[0], height = ii[1], width = ii[2], scale = ii[3];
    float wx = __fsub_rn(width, 1.0f);
    float hy = __fsub_rn(height, 1.0f);
    float sz = __fsub_rn(slices, 1.0f);
    float x1 = fminf(fmaxf(__fsub_rn(pcx, __fmul_rn(0.5f, pw)), 0.0f), wx);
    float y1 = fminf(fmaxf(__fsub_rn(pcy, __fmul_rn(0.5f, ph)), 0.0f), hy);
    float z1 = fminf(fmaxf(__fsub_rn(pcz, __fmul_rn(0.5f, pd)), 0.0f), sz);
    float x2 = fminf(fmaxf(__fsub_rn(__fadd_rn(pcx, __fmul_rn(0.5f, pw)), 1.0f), 0.0f), wx);
    float y2 = fminf(fmaxf(__fsub_rn(__fadd_rn(pcy, __fmul_rn(0.5f, ph)), 1.0f), 0.0f), hy);
    float z2 = fminf(fmaxf(__fsub_rn(__fadd_rn(pcz, __fmul_rn(0.5f, pd)), 1.0f), 0.0f), sz);
    // size/center filter (uses x-side for all dims, as reference does)
    float ss_ = __fadd_rn(__fsub_rn(x2, x1), 1.0f);
    float xc = __fadd_rn(x1, __fmul_rn(ss_, 0.5f));
    float yc = __fadd_rn(y1, __fmul_rn(ss_, 0.5f));
    float zc = __fadd_rn(z1, __fmul_rn(ss_, 0.5f));
    float minsz = __fmul_rn(8.0f, scale);
    int valid = (ss_ >= minsz) && (xc < width) && (yc < height) && (zc < slices);
    float vx = ss_;
    float vy = __fadd_rn(__fsub_rn(y2, y1), 1.0f);
    float vz = __fadd_rn(__fsub_rn(z2, z1), 1.0f);
    float vol = __fmul_rn(__fmul_rn(vx, vy), vz);
    g_bx1[r] = x1; g_by1[r] = y1; g_bz1[r] = z1;
    g_bx2[r] = x2; g_by2[r] = y2; g_bz2[r] = z2;
    g_volv[r] = vol;
    g_valid[r] = valid;
}

__global__ void mask_k() {
    __shared__ float cx1[64], cy1[64], cz1[64], cx2[64], cy2[64], cz2[64], cv[64];
    int word = blockIdx.x;              // 0..31
    int t = threadIdx.x;                // 128 threads
    if (t < 64) {
        int c = word*64 + t;
        if (c < PRE) {
            cx1[t] = g_bx1[c]; cy1[t] = g_by1[c]; cz1[t] = g_bz1[c];
            cx2[t] = g_bx2[c]; cy2[t] = g_by2[c]; cz2[t] = g_bz2[c];
            cv[t]  = g_volv[c];
        }
    }
    __syncthreads();
    int r = blockIdx.y*blockDim.x + t;
    if (r >= PRE) return;
    float x1 = g_bx1[r], y1 = g_by1[r], z1 = g_bz1[r];
    float x2 = g_bx2[r], y2 = g_by2[r], z2 = g_bz2[r];
    float vr = g_volv[r];
    unsigned long long bits = 0ull;
    #pragma unroll 8
    for (int c = 0; c < 64; ++c) {
        int j = word*64 + c;
        if (j < PRE && j > r) {
            float iw = fmaxf(__fadd_rn(__fsub_rn(fminf(x2, cx2[c]), fmaxf(x1, cx1[c])), 1.0f), 0.0f);
            float ih = fmaxf(__fadd_rn(__fsub_rn(fminf(y2, cy2[c]), fmaxf(y1, cy1[c])), 1.0f), 0.0f);
            float id = fmaxf(__fadd_rn(__fsub_rn(fminf(z2, cz2[c]), fmaxf(z1, cz1[c])), 1.0f), 0.0f);
            float inter = __fmul_rn(__fmul_rn(iw, ih), id);
            float denom = __fsub_rn(__fadd_rn(vr, cv[c]), inter);
            float iou = __fdiv_rn(inter, denom);
            if (iou > NMS_T) bits |= (1ull << c);
        }
    }
    g_mask[(size_t)r*WORDS + word] = bits;
}

__global__ void nmsred_k() {
    int lane = threadIdx.x;             // 32 lanes, lane owns word 'lane'
    unsigned long long rm = 0ull;
    for (int b = 0; b < 64; ++b) {
        int j = lane*64 + b;
        int inval = (j < PRE) ? (g_valid[j] ? 0 : 1) : 1;
        rm |= ((unsigned long long)inval) << b;
    }
    unsigned long long cur = g_mask[lane];
    for (int i = 0; i < PRE; ++i) {
        unsigned long long nxt = (i+1 < PRE) ? g_mask[(size_t)(i+1)*WORDS + lane] : 0ull;
        unsigned long long wv = __shfl_sync(0xffffffffu, rm, i >> 6);
        if (!((wv >> (i & 63)) & 1ull)) rm |= cur;
        cur = nxt;
    }
    g_remv[lane] = rm;
}

__device__ __forceinline__ void fill_one(float* out, int i, int pos) {
    int base = pos*7;
    out[base+0] = 0.0f;
    out[base+1] = g_bx1[i];
    out[base+2] = g_by1[i];
    out[base+3] = g_bz1[i];
    out[base+4] = g_bx2[i];
    out[base+5] = g_by2[i];
    out[base+6] = g_bz2[i];
    out[POST*7 + pos] = g_score[i];          // 2100..2399
    out[POST*8 + pos] = (float)g_order[i];   // 2400..2699
    out[POST*9 + pos] = 1.0f;                // 2700..2999
}

__global__ void output_k(float* __restrict__ out, int out_size) {
    __shared__ int sc[1024];
    __shared__ unsigned long long rw[WORDS];
    int t = threadIdx.x;
    if (t < WORDS) rw[t] = g_remv[t];
    // default init: rois+scores = 0, keep_idx = -1, sel_valid = 0
    for (int o = t; o < POST*8; o += 1024) if (o < out_size) out[o] = 0.0f;
    for (int o = t; o < POST; o += 1024) {
        if (POST*8 + o < out_size) out[POST*8 + o] = -1.0f;
        if (POST*9 + o < out_size) out[POST*9 + o] = 0.0f;
    }
    __syncthreads();
    int i0 = 2*t, i1 = 2*t + 1;
    int k0 = 0, k1 = 0;
    if (i0 < PRE) k0 = (g_valid[i0] && !((rw[i0>>6] >> (i0 & 63)) & 1ull)) ? 1 : 0;
    if (i1 < PRE) k1 = (g_valid[i1] && !((rw[i1>>6] >> (i1 & 63)) & 1ull)) ? 1 : 0;
    sc[t] = k0 + k1;
    __syncthreads();
    for (int off = 1; off < 1024; off <<= 1) {
        int v = (t >= off) ? sc[t-off] : 0;
        __syncthreads();
        sc[t] += v;
        __syncthreads();
    }
    int excl = sc[t] - (k0 + k1);
    if (out_size >= POST*10) {
        if (k0 && excl < POST)        fill_one(out, i0, excl);
        if (k1 && excl + k0 < POST)   fill_one(out, i1, excl + k0);
    }
}

// ---------------- launch ----------------
extern "C" void kernel_launch(void* const* d_in, const int* in_sizes, int n_in,
                              void* d_out, int out_size) {
    const float* scores  = (const float*)d_in[0];
    const float* deltas  = (const float*)d_in[1];
    const float* iminfo  = (const float*)d_in[2];
    const float* anchors = (const float*)d_in[3];
    float* out = (float*)d_out;

    init_k<<<64, 512>>>();
    hist1_k<<<1536, 512>>>(scores);
    resolve1_k<<<1, 1024>>>();
    hist2_k<<<1536, 512>>>(scores);
    resolve2_k<<<1, 1024>>>();
    compact_k<<<1536, 512>>>(scores);
    sort_k<<<1, 1024>>>();
    transform_k<<<(PRE + 255)/256, 256>>>(deltas, iminfo, anchors);
    mask_k<<<dim3(WORDS, (PRE + 127)/128), 128>>>();
    nmsred_k<<<1, 32>>>();
    output_k<<<1, 1024>>>(out, out_size);
}

// round 3
// speedup vs baseline: 1.1966x; 1.1966x over previous
#include <cuda_runtime.h>
#include <cstdint>

// Problem constants
#define AN 3
#define SSZ 32
#define HH 128
#define WW 128
#define KK (SSZ*HH*WW)        // 524288 spatial positions
#define NN (KK*AN)            // 1572864 total anchors
#define PRE 2000
#define POST 300
#define WORDS 32              // 2048 bits >= PRE
#define CAP 4096
#define NMS_T 0.7f

// ---------------- device state ----------------
__device__ unsigned int g_hist1[65536];
__device__ unsigned int g_hist2[65536];
__device__ unsigned int g_hiBin;
__device__ unsigned int g_need2;
__device__ unsigned int g_T;
__device__ int          g_cand_count;
__device__ unsigned long long g_cand[CAP];

__device__ int   g_order[PRE];
__device__ float g_score[PRE];
__device__ float g_bx1[PRE], g_by1[PRE], g_bz1[PRE];
__device__ float g_bx2[PRE], g_by2[PRE], g_bz2[PRE];
__device__ float g_volv[PRE];
__device__ int   g_valid[PRE];
__device__ unsigned long long g_mask[PRE*WORDS];
__device__ unsigned long long g_remv[WORDS];

// ---------------- kernels ----------------
__global__ void init_k() {
    int t = blockIdx.x*blockDim.x + threadIdx.x;
    int stride = gridDim.x*blockDim.x;
    for (int o = t; o < 65536; o += stride) { g_hist1[o] = 0u; g_hist2[o] = 0u; }
    if (t == 0) g_cand_count = 0;
}

__global__ void hist1_k(const float* __restrict__ sc) {
    int stride = gridDim.x*blockDim.x;
    for (int t = blockIdx.x*blockDim.x + threadIdx.x; t < NN; t += stride) {
        unsigned b = __float_as_uint(sc[t]);
        atomicAdd(&g_hist1[b >> 16], 1u);
    }
}

__global__ void resolve1_k() {
    __shared__ unsigned cs[1024];
    __shared__ unsigned ss[1024];
    int t = threadIdx.x;
    unsigned s = 0;
    #pragma unroll 8
    for (int m = 0; m < 64; ++m) s += g_hist1[t*64 + m];
    cs[t] = s;
    int r = 1023 - t;           // reversed index: r grows downward in bin value
    ss[r] = s;
    __syncthreads();
    for (int off = 1; off < 1024; off <<= 1) {
        unsigned v = (r >= off) ? ss[r-off] : 0u;
        __syncthreads();
        ss[r] += v;
        __syncthreads();
    }
    unsigned need = PRE;
    unsigned incl = ss[r];              // sum over chunks >= t
    unsigned above = incl - cs[t];      // sum over chunks  > t
    if (above < need && need <= incl) {
        unsigned c = above;
        for (int m = 63; m >= 0; --m) {
            unsigned h = g_hist1[t*64 + m];
            if (c + h >= need) { g_hiBin = (unsigned)(t*64 + m); g_need2 = need - c; break; }
            c += h;
        }
    }
}

__global__ void hist2_k(const float* __restrict__ sc) {
    unsigned hi = g_hiBin;
    int stride = gridDim.x*blockDim.x;
    for (int t = blockIdx.x*blockDim.x + threadIdx.x; t < NN; t += stride) {
        unsigned b = __float_as_uint(sc[t]);
        if ((b >> 16) == hi) atomicAdd(&g_hist2[b & 0xFFFFu], 1u);
    }
}

__global__ void resolve2_k() {
    __shared__ unsigned cs[1024];
    __shared__ unsigned ss[1024];
    int t = threadIdx.x;
    unsigned s = 0;
    #pragma unroll 8
    for (int m = 0; m < 64; ++m) s += g_hist2[t*64 + m];
    cs[t] = s;
    int r = 1023 - t;
    ss[r] = s;
    __syncthreads();
    for (int off = 1; off < 1024; off <<= 1) {
        unsigned v = (r >= off) ? ss[r-off] : 0u;
        __syncthreads();
        ss[r] += v;
        __syncthreads();
    }
    unsigned need = g_need2;
    unsigned incl = ss[r];
    unsigned above = incl - cs[t];
    if (above < need && need <= incl) {
        unsigned c = above;
        for (int m = 63; m >= 0; --m) {
            unsigned h = g_hist2[t*64 + m];
            if (c + h >= need) { g_T = (g_hiBin << 16) | (unsigned)(t*64 + m); break; }
            c += h;
        }
    }
}

__global__ void compact_k(const float* __restrict__ sc) {
    unsigned T = g_T;
    int stride = gridDim.x*blockDim.x;
    for (int t = blockIdx.x*blockDim.x + threadIdx.x; t < NN; t += stride) {
        unsigned b = __float_as_uint(sc[t]);
        if (b >= T) {
            int a = t / KK;
            int p = t - a*KK;
            unsigned i = (unsigned)(p*3 + a);
            int pos = atomicAdd(&g_cand_count, 1);
            if (pos < CAP)
                g_cand[pos] = ((unsigned long long)b << 32) |
                              (unsigned long long)(0xFFFFFFFFu - i);
        }
    }
}

__global__ void sort_k() {
    __shared__ unsigned long long sk[CAP];
    int t = threadIdx.x;
    int cnt = g_cand_count; if (cnt > CAP) cnt = CAP;
    for (int idx = t; idx < CAP; idx += 1024) sk[idx] = (idx < cnt) ? g_cand[idx] : 0ull;
    __syncthreads();
    for (int k = 2; k <= CAP; k <<= 1) {
        for (int j = k >> 1; j > 0; j >>= 1) {
            for (int idx = t; idx < CAP; idx += 1024) {
                int l = idx ^ j;
                if (l > idx) {
                    bool desc = ((idx & k) == 0);
                    unsigned long long a = sk[idx], b = sk[l];
                    bool sw = desc ? (a < b) : (a > b);
                    if (sw) { sk[idx] = b; sk[l] = a; }
                }
            }
            __syncthreads();
        }
    }
    for (int r = t; r < PRE; r += 1024) {
        unsigned long long key = sk[r];
        g_order[r] = (int)(0xFFFFFFFFu - (unsigned)(key & 0xFFFFFFFFull));
        g_score[r] = __uint_as_float((unsigned)(key >> 32));
    }
}

__global__ void transform_k(const float* __restrict__ deltas,
                            const float* __restrict__ ii,
                            const float* __restrict__ anc) {
    int r = blockIdx.x*blockDim.x + threadIdx.x;
    if (r >= PRE) return;
    int i = g_order[r];
    int a = i % 3;
    int p = i / 3;
    int w = p % WW;
    int h = (p / WW) % HH;
    int s = p / (WW*HH);
    float shx = 4.0f * (float)w, shy = 4.0f * (float)h, shz = 4.0f * (float)s;
    float x1a = __fadd_rn(shx, anc[a*6+0]);
    float y1a = __fadd_rn(shy, anc[a*6+1]);
    float z1a = __fadd_rn(shz, anc[a*6+2]);
    float x2a = __fadd_rn(shx, anc[a*6+3]);
    float y2a = __fadd_rn(shy, anc[a*6+4]);
    float z2a = __fadd_rn(shz, anc[a*6+5]);
    float ww_ = __fadd_rn(__fsub_rn(x2a, x1a), 1.0f);
    float hh_ = __fadd_rn(__fsub_rn(y2a, y1a), 1.0f);
    float dd_ = __fadd_rn(__fsub_rn(z2a, z1a), 1.0f);
    float cx = __fadd_rn(x1a, __fmul_rn(0.5f, ww_));
    float cy = __fadd_rn(y1a, __fmul_rn(0.5f, hh_));
    float cz = __fadd_rn(z1a, __fmul_rn(0.5f, dd_));
    const float* dp = deltas + p;
    float dx = dp[(6*a+0)*KK];
    float dy = dp[(6*a+1)*KK];
    float dz = dp[(6*a+2)*KK];
    float dw = dp[(6*a+3)*KK];
    float dh = dp[(6*a+4)*KK];
    float dd = dp[(6*a+5)*KK];
    float pcx = __fadd_rn(__fmul_rn(dx, ww_), cx);
    float pcy = __fadd_rn(__fmul_rn(dy, hh_), cy);
    float pcz = __fadd_rn(__fmul_rn(dz, dd_), cz);
    float pw = __fmul_rn(expf(dw), ww_);
    float ph = __fmul_rn(expf(dh), hh_);
    float pd = __fmul_rn(expf(dd), dd_);
    float slices = ii[0], height = ii[1], width = ii[2], scale = ii[3];
    float wx = __fsub_rn(width, 1.0f);
    float hy = __fsub_rn(height, 1.0f);
    float sz = __fsub_rn(slices, 1.0f);
    float x1 = fminf(fmaxf(__fsub_rn(pcx, __fmul_rn(0.5f, pw)), 0.0f), wx);
    float y1 = fminf(fmaxf(__fsub_rn(pcy, __fmul_rn(0.5f, ph)), 0.0f), hy);
    float z1 = fminf(fmaxf(__fsub_rn(pcz, __fmul_rn(0.5f, pd)), 0.0f), sz);
    float x2 = fminf(fmaxf(__fsub_rn(__fadd_rn(pcx, __fmul_rn(0.5f, pw)), 1.0f), 0.0f), wx);
    float y2 = fminf(fmaxf(__fsub_rn(__fadd_rn(pcy, __fmul_rn(0.5f, ph)), 1.0f), 0.0f), hy);
    float z2 = fminf(fmaxf(__fsub_rn(__fadd_rn(pcz, __fmul_rn(0.5f, pd)), 1.0f), 0.0f), sz);
    // size/center filter (uses x-side for all dims, as reference does)
    float ss_ = __fadd_rn(__fsub_rn(x2, x1), 1.0f);
    float xc = __fadd_rn(x1, __fmul_rn(ss_, 0.5f));
    float yc = __fadd_rn(y1, __fmul_rn(ss_, 0.5f));
    float zc = __fadd_rn(z1, __fmul_rn(ss_, 0.5f));
    float minsz = __fmul_rn(8.0f, scale);
    int valid = (ss_ >= minsz) && (xc < width) && (yc < height) && (zc < slices);
    float vx = ss_;
    float vy = __fadd_rn(__fsub_rn(y2, y1), 1.0f);
    float vz = __fadd_rn(__fsub_rn(z2, z1), 1.0f);
    float vol = __fmul_rn(__fmul_rn(vx, vy), vz);
    g_bx1[r] = x1; g_by1[r] = y1; g_bz1[r] = z1;
    g_bx2[r] = x2; g_by2[r] = y2; g_bz2[r] = z2;
    g_volv[r] = vol;
    g_valid[r] = valid;
}

__global__ void mask_k() {
    __shared__ float cx1[64], cy1[64], cz1[64], cx2[64], cy2[64], cz2[64], cv[64];
    int word = blockIdx.x;              // 0..31
    int t = threadIdx.x;                // 128 threads
    if (t < 64) {
        int c = word*64 + t;
        if (c < PRE) {
            cx1[t] = g_bx1[c]; cy1[t] = g_by1[c]; cz1[t] = g_bz1[c];
            cx2[t] = g_bx2[c]; cy2[t] = g_by2[c]; cz2[t] = g_bz2[c];
            cv[t]  = g_volv[c];
        }
    }
    __syncthreads();
    int r = blockIdx.y*blockDim.x + t;
    if (r >= PRE) return;
    float x1 = g_bx1[r], y1 = g_by1[r], z1 = g_bz1[r];
    float x2 = g_bx2[r], y2 = g_by2[r], z2 = g_bz2[r];
    float vr = g_volv[r];
    unsigned long long bits = 0ull;
    #pragma unroll 8
    for (int c = 0; c < 64; ++c) {
        int j = word*64 + c;
        if (j < PRE && j > r) {
            float iw = fmaxf(__fadd_rn(__fsub_rn(fminf(x2, cx2[c]), fmaxf(x1, cx1[c])), 1.0f), 0.0f);
            float ih = fmaxf(__fadd_rn(__fsub_rn(fminf(y2, cy2[c]), fmaxf(y1, cy1[c])), 1.0f), 0.0f);
            float id = fmaxf(__fadd_rn(__fsub_rn(fminf(z2, cz2[c]), fmaxf(z1, cz1[c])), 1.0f), 0.0f);
            float inter = __fmul_rn(__fmul_rn(iw, ih), id);
            float denom = __fsub_rn(__fadd_rn(vr, cv[c]), inter);
            float iou = __fdiv_rn(inter, denom);
            if (iou > NMS_T) bits |= (1ull << c);
        }
    }
    g_mask[(size_t)r*WORDS + word] = bits;
}

// Greedy NMS reduce, 1 warp. Lane k owns suppression word k (64 bits).
// Process candidates in chunks of 16 (all within one 64-bit word since 16|64).
// The owning lane decides accept bits serially from its local word (no shfl in
// the chain); one shfl broadcasts the 16-bit accept mask; all lanes then apply
// idempotent ORs of the prefetched rows. Next chunk's 16 rows are prefetched
// into registers while the current chunk is processed (hides L2 latency).
__global__ void nmsred_k() {
    int lane = threadIdx.x;             // 32 lanes
    unsigned long long rm = 0ull;       // suppression word 'lane'
    #pragma unroll
    for (int b = 0; b < 64; ++b) {
        int j = lane*64 + b;
        int inval = (j < PRE) ? (g_valid[j] ? 0 : 1) : 1;
        rm |= ((unsigned long long)inval) << b;
    }
    const int NCH = (PRE + 15) / 16;    // 125 chunks
    unsigned long long v[16], nx[16];
    #pragma unroll
    for (int b = 0; b < 16; ++b)
        v[b] = g_mask[(size_t)b*WORDS + lane];
    for (int c = 0; c < NCH; ++c) {
        int nbase = (c + 1) * 16;
        #pragma unroll
        for (int b = 0; b < 16; ++b) {
            int row = nbase + b;
            nx[b] = (row < PRE) ? g_mask[(size_t)row*WORDS + lane] : 0ull;
        }
        int w  = (c * 16) >> 6;         // word holding these 16 candidates
        int sh = (c * 16) & 63;         // bit offset within the word
        unsigned acc = 0u;
        if (lane == w) {
            #pragma unroll
            for (int b = 0; b < 16; ++b) {
                if (!((rm >> (sh + b)) & 1ull)) { acc |= (1u << b); rm |= v[b]; }
            }
        }
        acc = __shfl_sync(0xffffffffu, acc, w);
        #pragma unroll
        for (int b = 0; b < 16; ++b)
            if ((acc >> b) & 1u) rm |= v[b];
        #pragma unroll
        for (int b = 0; b < 16; ++b) v[b] = nx[b];
    }
    g_remv[lane] = rm;
}

__device__ __forceinline__ void fill_one(float* out, int i, int pos) {
    int base = pos*7;
    out[base+0] = 0.0f;
    out[base+1] = g_bx1[i];
    out[base+2] = g_by1[i];
    out[base+3] = g_bz1[i];
    out[base+4] = g_bx2[i];
    out[base+5] = g_by2[i];
    out[base+6] = g_bz2[i];
    out[POST*7 + pos] = g_score[i];          // 2100..2399
    out[POST*8 + pos] = (float)g_order[i];   // 2400..2699
    out[POST*9 + pos] = 1.0f;                // 2700..2999
}

__global__ void output_k(float* __restrict__ out, int out_size) {
    __shared__ int sc[1024];
    __shared__ unsigned long long rw[WORDS];
    int t = threadIdx.x;
    if (t < WORDS) rw[t] = g_remv[t];
    // default init: rois+scores = 0, keep_idx = -1, sel_valid = 0
    for (int o = t; o < POST*8; o += 1024) if (o < out_size) out[o] = 0.0f;
    for (int o = t; o < POST; o += 1024) {
        if (POST*8 + o < out_size) out[POST*8 + o] = -1.0f;
        if (POST*9 + o < out_size) out[POST*9 + o] = 0.0f;
    }
    __syncthreads();
    int i0 = 2*t, i1 = 2*t + 1;
    int k0 = 0, k1 = 0;
    if (i0 < PRE) k0 = (g_valid[i0] && !((rw[i0>>6] >> (i0 & 63)) & 1ull)) ? 1 : 0;
    if (i1 < PRE) k1 = (g_valid[i1] && !((rw[i1>>6] >> (i1 & 63)) & 1ull)) ? 1 : 0;
    sc[t] = k0 + k1;
    __syncthreads();
    for (int off = 1; off < 1024; off <<= 1) {
        int v = (t >= off) ? sc[t-off] : 0;
        __syncthreads();
        sc[t] += v;
        __syncthreads();
    }
    int excl = sc[t] - (k0 + k1);
    if (out_size >= POST*10) {
        if (k0 && excl < POST)        fill_one(out, i0, excl);
        if (k1 && excl + k0 < POST)   fill_one(out, i1, excl + k0);
    }
}

// ---------------- launch ----------------
extern "C" void kernel_launch(void* const* d_in, const int* in_sizes, int n_in,
                              void* d_out, int out_size) {
    const float* scores  = (const float*)d_in[0];
    const float* deltas  = (const float*)d_in[1];
    const float* iminfo  = (const float*)d_in[2];
    const float* anchors = (const float*)d_in[3];
    float* out = (float*)d_out;

    init_k<<<64, 512>>>();
    hist1_k<<<1536, 512>>>(scores);
    resolve1_k<<<1, 1024>>>();
    hist2_k<<<1536, 512>>>(scores);
    resolve2_k<<<1, 1024>>>();
    compact_k<<<1536, 512>>>(scores);
    sort_k<<<1, 1024>>>();
    transform_k<<<(PRE + 255)/256, 256>>>(deltas, iminfo, anchors);
    mask_k<<<dim3(WORDS, (PRE + 127)/128), 128>>>();
    nmsred_k<<<1, 32>>>();
    output_k<<<1, 1024>>>(out, out_size);
}

// round 4
// speedup vs baseline: 3.3153x; 2.7706x over previous
#include <cuda_runtime.h>
#include <cstdint>

// Problem constants
#define AN 3
#define SSZ 32
#define HH 128
#define WW 128
#define KK (SSZ*HH*WW)        // 524288 spatial positions
#define NN (KK*AN)            // 1572864 total anchors
#define PRE 2000
#define POST 300
#define WORDS 32              // 2048 bits >= PRE
#define CAP 4096
#define NMS_T 0.7f
#define TC 0.99834f           // static stash threshold (fast path)

// ---------------- device state ----------------
__device__ unsigned int g_hist1[65536];
__device__ unsigned int g_hist2[65536];
__device__ unsigned int g_hiBin;
__device__ unsigned int g_need2;
__device__ unsigned int g_T;
__device__ int          g_cand_count;
__device__ int          g_fb;
__device__ unsigned long long g_cand[CAP];

__device__ int   g_order[PRE];
__device__ float g_score[PRE];
__device__ float g_bx1[PRE], g_by1[PRE], g_bz1[PRE];
__device__ float g_bx2[PRE], g_by2[PRE], g_bz2[PRE];
__device__ float g_volv[PRE];
__device__ int   g_valid[PRE];
__device__ unsigned long long g_mask[PRE*WORDS];
__device__ unsigned long long g_remv[WORDS];

// ---------------- helpers ----------------
__device__ __forceinline__ void stash_one(int t, unsigned b) {
    int a = t / KK;
    int p = t - a*KK;
    unsigned i = (unsigned)(p*3 + a);
    int pos = atomicAdd(&g_cand_count, 1);
    if (pos < CAP)
        g_cand[pos] = ((unsigned long long)b << 32) |
                      (unsigned long long)(0xFFFFFFFFu - i);
}

// ---------------- kernels ----------------
__global__ void init0_k() {
    if (threadIdx.x == 0) { g_cand_count = 0; g_fb = 0; }
}

// Fast path: one pass, stash everything >= TC.
__global__ void scan_k(const float4* __restrict__ sc) {
    int stride = gridDim.x*blockDim.x;
    for (int t = blockIdx.x*blockDim.x + threadIdx.x; t < NN/4; t += stride) {
        float4 v = sc[t];
        if (v.x >= TC) stash_one(4*t+0, __float_as_uint(v.x));
        if (v.y >= TC) stash_one(4*t+1, __float_as_uint(v.y));
        if (v.z >= TC) stash_one(4*t+2, __float_as_uint(v.z));
        if (v.w >= TC) stash_one(4*t+3, __float_as_uint(v.w));
    }
}

// Decide fallback; if needed, zero hists and reset count.
__global__ void fbcheck_k() {
    int cnt = g_cand_count;
    int fb = (cnt < PRE) || (cnt > CAP);
    if (threadIdx.x == 0) g_fb = fb;
    if (fb) {
        for (int o = threadIdx.x; o < 65536; o += blockDim.x) {
            g_hist1[o] = 0u; g_hist2[o] = 0u;
        }
        if (threadIdx.x == 0) g_cand_count = 0;
    }
}

__global__ void fb_hist1_k(const float* __restrict__ sc) {
    if (g_fb == 0) return;
    int stride = gridDim.x*blockDim.x;
    for (int t = blockIdx.x*blockDim.x + threadIdx.x; t < NN; t += stride) {
        unsigned b = __float_as_uint(sc[t]);
        atomicAdd(&g_hist1[b >> 16], 1u);
    }
}

__global__ void fb_res1_k() {
    if (g_fb == 0) return;
    __shared__ unsigned cs[1024];
    __shared__ unsigned ss[1024];
    int t = threadIdx.x;
    unsigned s = 0;
    #pragma unroll 8
    for (int m = 0; m < 64; ++m) s += g_hist1[t*64 + m];
    cs[t] = s;
    int r = 1023 - t;
    ss[r] = s;
    __syncthreads();
    for (int off = 1; off < 1024; off <<= 1) {
        unsigned v = (r >= off) ? ss[r-off] : 0u;
        __syncthreads();
        ss[r] += v;
        __syncthreads();
    }
    unsigned need = PRE;
    unsigned incl = ss[r];
    unsigned above = incl - cs[t];
    if (above < need && need <= incl) {
        unsigned c = above;
        for (int m = 63; m >= 0; --m) {
            unsigned h = g_hist1[t*64 + m];
            if (c + h >= need) { g_hiBin = (unsigned)(t*64 + m); g_need2 = need - c; break; }
            c += h;
        }
    }
}

__global__ void fb_hist2_k(const float* __restrict__ sc) {
    if (g_fb == 0) return;
    unsigned hi = g_hiBin;
    int stride = gridDim.x*blockDim.x;
    for (int t = blockIdx.x*blockDim.x + threadIdx.x; t < NN; t += stride) {
        unsigned b = __float_as_uint(sc[t]);
        if ((b >> 16) == hi) atomicAdd(&g_hist2[b & 0xFFFFu], 1u);
    }
}

__global__ void fb_res2_k() {
    if (g_fb == 0) return;
    __shared__ unsigned cs[1024];
    __shared__ unsigned ss[1024];
    int t = threadIdx.x;
    unsigned s = 0;
    #pragma unroll 8
    for (int m = 0; m < 64; ++m) s += g_hist2[t*64 + m];
    cs[t] = s;
    int r = 1023 - t;
    ss[r] = s;
    __syncthreads();
    for (int off = 1; off < 1024; off <<= 1) {
        unsigned v = (r >= off) ? ss[r-off] : 0u;
        __syncthreads();
        ss[r] += v;
        __syncthreads();
    }
    unsigned need = g_need2;
    unsigned incl = ss[r];
    unsigned above = incl - cs[t];
    if (above < need && need <= incl) {
        unsigned c = above;
        for (int m = 63; m >= 0; --m) {
            unsigned h = g_hist2[t*64 + m];
            if (c + h >= need) { g_T = (g_hiBin << 16) | (unsigned)(t*64 + m); break; }
            c += h;
        }
    }
}

__global__ void fb_compact_k(const float* __restrict__ sc) {
    if (g_fb == 0) return;
    unsigned T = g_T;
    int stride = gridDim.x*blockDim.x;
    for (int t = blockIdx.x*blockDim.x + threadIdx.x; t < NN; t += stride) {
        unsigned b = __float_as_uint(sc[t]);
        if (b >= T) stash_one(t, b);
    }
}

// All-pairs rank + fused box transform. Keys are unique -> ranks are a
// permutation; rank < PRE elements are the exact sorted top-PRE.
__global__ void rank_k(const float* __restrict__ deltas,
                       const float* __restrict__ ii,
                       const float* __restrict__ anc) {
    __shared__ unsigned long long tile[256];
    int cnt = g_cand_count; if (cnt > CAP) cnt = CAP;
    int i = blockIdx.x*256 + threadIdx.x;
    if (blockIdx.x*256 >= cnt) return;
    unsigned long long my = (i < cnt) ? g_cand[i] : 0xFFFFFFFFFFFFFFFFull;
    int rank = 0;
    for (int base = 0; base < cnt; base += 256) {
        int j = base + threadIdx.x;
        tile[threadIdx.x] = (j < cnt) ? g_cand[j] : 0ull;   // 0 never counts
        __syncthreads();
        #pragma unroll 8
        for (int k = 0; k < 256; ++k) rank += (tile[k] > my) ? 1 : 0;
        __syncthreads();
    }
    if (i >= cnt || rank >= PRE) return;

    int idx = (int)(0xFFFFFFFFu - (unsigned)(my & 0xFFFFFFFFull));
    float score = __uint_as_float((unsigned)(my >> 32));
    int r = rank;
    int a = idx % 3;
    int p = idx / 3;
    int w = p % WW;
    int h = (p / WW) % HH;
    int s = p / (WW*HH);
    float shx = 4.0f * (float)w, shy = 4.0f * (float)h, shz = 4.0f * (float)s;
    float x1a = __fadd_rn(shx, anc[a*6+0]);
    float y1a = __fadd_rn(shy, anc[a*6+1]);
    float z1a = __fadd_rn(shz, anc[a*6+2]);
    float x2a = __fadd_rn(shx, anc[a*6+3]);
    float y2a = __fadd_rn(shy, anc[a*6+4]);
    float z2a = __fadd_rn(shz, anc[a*6+5]);
    float ww_ = __fadd_rn(__fsub_rn(x2a, x1a), 1.0f);
    float hh_ = __fadd_rn(__fsub_rn(y2a, y1a), 1.0f);
    float dd_ = __fadd_rn(__fsub_rn(z2a, z1a), 1.0f);
    float cx = __fadd_rn(x1a, __fmul_rn(0.5f, ww_));
    float cy = __fadd_rn(y1a, __fmul_rn(0.5f, hh_));
    float cz = __fadd_rn(z1a, __fmul_rn(0.5f, dd_));
    const float* dp = deltas + p;
    float dx = dp[(6*a+0)*KK];
    float dy = dp[(6*a+1)*KK];
    float dz = dp[(6*a+2)*KK];
    float dw = dp[(6*a+3)*KK];
    float dh = dp[(6*a+4)*KK];
    float dd = dp[(6*a+5)*KK];
    float pcx = __fadd_rn(__fmul_rn(dx, ww_), cx);
    float pcy = __fadd_rn(__fmul_rn(dy, hh_), cy);
    float pcz = __fadd_rn(__fmul_rn(dz, dd_), cz);
    float pw = __fmul_rn(expf(dw), ww_);
    float ph = __fmul_rn(expf(dh), hh_);
    float pd = __fmul_rn(expf(dd), dd_);
    float slices = ii[0], height = ii[1], width = ii[2], scale = ii[3];
    float wx = __fsub_rn(width, 1.0f);
    float hy = __fsub_rn(height, 1.0f);
    float sz = __fsub_rn(slices, 1.0f);
    float x1 = fminf(fmaxf(__fsub_rn(pcx, __fmul_rn(0.5f, pw)), 0.0f), wx);
    float y1 = fminf(fmaxf(__fsub_rn(pcy, __fmul_rn(0.5f, ph)), 0.0f), hy);
    float z1 = fminf(fmaxf(__fsub_rn(pcz, __fmul_rn(0.5f, pd)), 0.0f), sz);
    float x2 = fminf(fmaxf(__fsub_rn(__fadd_rn(pcx, __fmul_rn(0.5f, pw)), 1.0f), 0.0f), wx);
    float y2 = fminf(fmaxf(__fsub_rn(__fadd_rn(pcy, __fmul_rn(0.5f, ph)), 1.0f), 0.0f), hy);
    float z2 = fminf(fmaxf(__fsub_rn(__fadd_rn(pcz, __fmul_rn(0.5f, pd)), 1.0f), 0.0f), sz);
    float ss_ = __fadd_rn(__fsub_rn(x2, x1), 1.0f);
    float xc = __fadd_rn(x1, __fmul_rn(ss_, 0.5f));
    float yc = __fadd_rn(y1, __fmul_rn(ss_, 0.5f));
    float zc = __fadd_rn(z1, __fmul_rn(ss_, 0.5f));
    float minsz = __fmul_rn(8.0f, scale);
    int valid = (ss_ >= minsz) && (xc < width) && (yc < height) && (zc < slices);
    float vy = __fadd_rn(__fsub_rn(y2, y1), 1.0f);
    float vz = __fadd_rn(__fsub_rn(z2, z1), 1.0f);
    float vol = __fmul_rn(__fmul_rn(ss_, vy), vz);
    g_bx1[r] = x1; g_by1[r] = y1; g_bz1[r] = z1;
    g_bx2[r] = x2; g_by2[r] = y2; g_bz2[r] = z2;
    g_volv[r] = vol;
    g_valid[r] = valid;
    g_order[r] = idx;
    g_score[r] = score;
}

__global__ void mask_k() {
    __shared__ float cx1[64], cy1[64], cz1[64], cx2[64], cy2[64], cz2[64], cv[64];
    int word = blockIdx.x;              // 0..31
    int t = threadIdx.x;                // 128 threads
    if (t < 64) {
        int c = word*64 + t;
        if (c < PRE) {
            cx1[t] = g_bx1[c]; cy1[t] = g_by1[c]; cz1[t] = g_bz1[c];
            cx2[t] = g_bx2[c]; cy2[t] = g_by2[c]; cz2[t] = g_bz2[c];
            cv[t]  = g_volv[c];
        }
    }
    __syncthreads();
    int r = blockIdx.y*blockDim.x + t;
    if (r >= PRE) return;
    float x1 = g_bx1[r], y1 = g_by1[r], z1 = g_bz1[r];
    float x2 = g_bx2[r], y2 = g_by2[r], z2 = g_bz2[r];
    float vr = g_volv[r];
    unsigned long long bits = 0ull;
    #pragma unroll 8
    for (int c = 0; c < 64; ++c) {
        int j = word*64 + c;
        if (j < PRE && j > r) {
            float iw = fmaxf(__fadd_rn(__fsub_rn(fminf(x2, cx2[c]), fmaxf(x1, cx1[c])), 1.0f), 0.0f);
            float ih = fmaxf(__fadd_rn(__fsub_rn(fminf(y2, cy2[c]), fmaxf(y1, cy1[c])), 1.0f), 0.0f);
            float id = fmaxf(__fadd_rn(__fsub_rn(fminf(z2, cz2[c]), fmaxf(z1, cz1[c])), 1.0f), 0.0f);
            float inter = __fmul_rn(__fmul_rn(iw, ih), id);
            float denom = __fsub_rn(__fadd_rn(vr, cv[c]), inter);
            float iou = __fdiv_rn(inter, denom);
            if (iou > NMS_T) bits |= (1ull << c);
        }
    }
    g_mask[(size_t)r*WORDS + word] = bits;
}

// Greedy NMS reduce, 1 warp, chunked 16 with register double-buffering and
// branchless SEL-based decide chain.
__global__ void nmsred_k() {
    int lane = threadIdx.x;             // 32 lanes
    unsigned long long rm = 0ull;       // suppression word 'lane'
    #pragma unroll
    for (int b = 0; b < 64; ++b) {
        int j = lane*64 + b;
        int inval = (j < PRE) ? (g_valid[j] ? 0 : 1) : 1;
        rm |= ((unsigned long long)inval) << b;
    }
    const int NCH = (PRE + 15) / 16;    // 125 chunks
    unsigned long long v[16], nx[16];
    #pragma unroll
    for (int b = 0; b < 16; ++b)
        v[b] = g_mask[(size_t)b*WORDS + lane];
    for (int c = 0; c < NCH; ++c) {
        int nbase = (c + 1) * 16;
        #pragma unroll
        for (int b = 0; b < 16; ++b) {
            int row = nbase + b;
            nx[b] = (row < PRE) ? g_mask[(size_t)row*WORDS + lane] : 0ull;
        }
        int w  = (c * 16) >> 6;
        int sh = (c * 16) & 63;
        unsigned acc = 0u;
        if (lane == w) {
            #pragma unroll
            for (int b = 0; b < 16; ++b) {
                unsigned sup = (unsigned)(rm >> (sh + b)) & 1u;
                acc |= (sup ^ 1u) << b;
                rm |= sup ? 0ull : v[b];
            }
        }
        acc = __shfl_sync(0xffffffffu, acc, w);
        #pragma unroll
        for (int b = 0; b < 16; ++b)
            rm |= ((acc >> b) & 1u) ? v[b] : 0ull;
        #pragma unroll
        for (int b = 0; b < 16; ++b) v[b] = nx[b];
    }
    g_remv[lane] = rm;
}

__device__ __forceinline__ void fill_one(float* out, int i, int pos) {
    int base = pos*7;
    out[base+0] = 0.0f;
    out[base+1] = g_bx1[i];
    out[base+2] = g_by1[i];
    out[base+3] = g_bz1[i];
    out[base+4] = g_bx2[i];
    out[base+5] = g_by2[i];
    out[base+6] = g_bz2[i];
    out[POST*7 + pos] = g_score[i];          // 2100..2399
    out[POST*8 + pos] = (float)g_order[i];   // 2400..2699
    out[POST*9 + pos] = 1.0f;                // 2700..2999
}

__global__ void output_k(float* __restrict__ out, int out_size) {
    __shared__ int sc[1024];
    __shared__ unsigned long long rw[WORDS];
    int t = threadIdx.x;
    if (t < WORDS) rw[t] = g_remv[t];
    for (int o = t; o < POST*8; o += 1024) if (o < out_size) out[o] = 0.0f;
    for (int o = t; o < POST; o += 1024) {
        if (POST*8 + o < out_size) out[POST*8 + o] = -1.0f;
        if (POST*9 + o < out_size) out[POST*9 + o] = 0.0f;
    }
    __syncthreads();
    int i0 = 2*t, i1 = 2*t + 1;
    int k0 = 0, k1 = 0;
    if (i0 < PRE) k0 = (g_valid[i0] && !((rw[i0>>6] >> (i0 & 63)) & 1ull)) ? 1 : 0;
    if (i1 < PRE) k1 = (g_valid[i1] && !((rw[i1>>6] >> (i1 & 63)) & 1ull)) ? 1 : 0;
    sc[t] = k0 + k1;
    __syncthreads();
    for (int off = 1; off < 1024; off <<= 1) {
        int v = (t >= off) ? sc[t-off] : 0;
        __syncthreads();
        sc[t] += v;
        __syncthreads();
    }
    int excl = sc[t] - (k0 + k1);
    if (out_size >= POST*10) {
        if (k0 && excl < POST)        fill_one(out, i0, excl);
        if (k1 && excl + k0 < POST)   fill_one(out, i1, excl + k0);
    }
}

// ---------------- launch ----------------
extern "C" void kernel_launch(void* const* d_in, const int* in_sizes, int n_in,
                              void* d_out, int out_size) {
    const float* scores  = (const float*)d_in[0];
    const float* deltas  = (const float*)d_in[1];
    const float* iminfo  = (const float*)d_in[2];
    const float* anchors = (const float*)d_in[3];
    float* out = (float*)d_out;

    init0_k<<<1, 32>>>();
    scan_k<<<768, 512>>>((const float4*)scores);
    fbcheck_k<<<1, 1024>>>();
    fb_hist1_k<<<1536, 512>>>(scores);
    fb_res1_k<<<1, 1024>>>();
    fb_hist2_k<<<1536, 512>>>(scores);
    fb_res2_k<<<1, 1024>>>();
    fb_compact_k<<<1536, 512>>>(scores);
    rank_k<<<CAP/256, 256>>>(deltas, iminfo, anchors);
    mask_k<<<dim3(WORDS, (PRE + 127)/128), 128>>>();
    nmsred_k<<<1, 32>>>();
    output_k<<<1, 1024>>>(out, out_size);
}

// round 7
// speedup vs baseline: 3.5758x; 1.0786x over previous
#include <cuda_runtime.h>
#include <cstdint>

// Problem constants
#define AN 3
#define SSZ 32
#define HH 128
#define WW 128
#define KK (SSZ*HH*WW)        // 524288 spatial positions
#define NN (KK*AN)            // 1572864 total anchors
#define PRE 2000
#define POST 300
#define WORDS 32              // 2048 bits >= PRE
#define CAP 4096
#define NMS_T 0.7f
#define TC 0.99834f           // static stash threshold (fast path)

typedef unsigned long long u64;

// ---------------- device state ----------------
__device__ unsigned int g_hist1[65536];
__device__ unsigned int g_hist2[65536];
__device__ int          g_cand_count;      // zero-init; reset by final_k
__device__ u64          g_cand[CAP];

__device__ int   g_order[PRE];
__device__ float g_score[PRE];
__device__ float g_bx1[PRE], g_by1[PRE], g_bz1[PRE];
__device__ float g_bx2[PRE], g_by2[PRE], g_bz2[PRE];
__device__ float g_volv[PRE];
__device__ int   g_valid[PRE];
__device__ u64   g_mask[PRE*WORDS];

// ---------------- kernels ----------------

// Fast path: one pass over scores, warp-aggregated stash of everything >= TC.
// Grid exactly covers NN/4 float4 elements (all warps full).
__global__ void __launch_bounds__(512) scan_k(const float4* __restrict__ sc) {
    int t = blockIdx.x*blockDim.x + threadIdx.x;
    float4 v = sc[t];
    unsigned m0 = __ballot_sync(0xffffffffu, v.x >= TC);
    unsigned m1 = __ballot_sync(0xffffffffu, v.y >= TC);
    unsigned m2 = __ballot_sync(0xffffffffu, v.z >= TC);
    unsigned m3 = __ballot_sync(0xffffffffu, v.w >= TC);
    int c0 = __popc(m0), c1 = __popc(m1), c2 = __popc(m2), c3 = __popc(m3);
    int tot = c0 + c1 + c2 + c3;
    if (tot == 0) return;
    int lane = threadIdx.x & 31;
    int base = 0;
    if (lane == 0) base = atomicAdd(&g_cand_count, tot);
    base = __shfl_sync(0xffffffffu, base, 0);
    unsigned lt = (1u << lane) - 1u;
    int off0 = base + __popc(m0 & lt);
    int off1 = base + c0 + __popc(m1 & lt);
    int off2 = base + c0 + c1 + __popc(m2 & lt);
    int off3 = base + c0 + c1 + c2 + __popc(m3 & lt);
    #pragma unroll
    for (int c = 0; c < 4; ++c) {
        float val = (c==0) ? v.x : (c==1) ? v.y : (c==2) ? v.z : v.w;
        int pos   = (c==0) ? off0 : (c==1) ? off1 : (c==2) ? off2 : off3;
        if (val >= TC && pos < CAP) {
            int g = 4*t + c;            // flat index in (A,S,H,W) layout
            int a = g / KK;
            int p = g - a*KK;
            unsigned i = (unsigned)(p*3 + a);
            g_cand[pos] = ((u64)__float_as_uint(val) << 32) |
                          (u64)(0xFFFFFFFFu - i);
        }
    }
}

// Exact fallback, single block. Early-exits (the normal case) when the stash
// count is usable. Otherwise: full 2-digit radix select + compact.
__global__ void __launch_bounds__(1024) fb_all_k(const float* __restrict__ sc) {
    int cnt0 = g_cand_count;
    if (cnt0 >= PRE && cnt0 <= CAP) return;

    __shared__ unsigned cs[1024];
    __shared__ unsigned ss[1024];
    __shared__ unsigned sh_hi, sh_need2, sh_T;
    int t = threadIdx.x;

    for (int o = t; o < 65536; o += 1024) { g_hist1[o] = 0u; g_hist2[o] = 0u; }
    __syncthreads();
    for (int i = t; i < NN; i += 1024) {
        unsigned b = __float_as_uint(sc[i]);
        atomicAdd(&g_hist1[b >> 16], 1u);
    }
    __syncthreads();
    // resolve pass 1
    {
        unsigned s = 0;
        for (int m = 0; m < 64; ++m) s += __ldcg(&g_hist1[t*64 + m]);
        cs[t] = s;
        int r = 1023 - t;
        ss[r] = s;
        __syncthreads();
        for (int off = 1; off < 1024; off <<= 1) {
            unsigned v = (r >= off) ? ss[r-off] : 0u;
            __syncthreads();
            ss[r] += v;
            __syncthreads();
        }
        unsigned need = PRE;
        unsigned incl = ss[r];
        unsigned above = incl - cs[t];
        if (above < need && need <= incl) {
            unsigned c = above;
            for (int m = 63; m >= 0; --m) {
                unsigned h = __ldcg(&g_hist1[t*64 + m]);
                if (c + h >= need) { sh_hi = (unsigned)(t*64 + m); sh_need2 = need - c; break; }
                c += h;
            }
        }
    }
    __syncthreads();
    unsigned hi = sh_hi;
    for (int i = t; i < NN; i += 1024) {
        unsigned b = __float_as_uint(sc[i]);
        if ((b >> 16) == hi) atomicAdd(&g_hist2[b & 0xFFFFu], 1u);
    }
    __syncthreads();
    // resolve pass 2
    {
        unsigned s = 0;
        for (int m = 0; m < 64; ++m) s += __ldcg(&g_hist2[t*64 + m]);
        cs[t] = s;
        int r = 1023 - t;
        ss[r] = s;
        __syncthreads();
        for (int off = 1; off < 1024; off <<= 1) {
            unsigned v = (r >= off) ? ss[r-off] : 0u;
            __syncthreads();
            ss[r] += v;
            __syncthreads();
        }
        unsigned need = sh_need2;
        unsigned incl = ss[r];
        unsigned above = incl - cs[t];
        if (above < need && need <= incl) {
            unsigned c = above;
            for (int m = 63; m >= 0; --m) {
                unsigned h = __ldcg(&g_hist2[t*64 + m]);
                if (c + h >= need) { sh_T = (hi << 16) | (unsigned)(t*64 + m); break; }
                c += h;
            }
        }
    }
    __syncthreads();
    if (t == 0) g_cand_count = 0;
    __syncthreads();
    unsigned T = sh_T;
    for (int i = t; i < NN; i += 1024) {
        unsigned b = __float_as_uint(sc[i]);
        if (b >= T) {
            int a = i / KK;
            int p = i - a*KK;
            unsigned id = (unsigned)(p*3 + a);
            int pos = atomicAdd(&g_cand_count, 1);
            if (pos < CAP)
                g_cand[pos] = ((u64)b << 32) | (u64)(0xFFFFFFFFu - id);
        }
    }
}

// All-pairs rank + fused box transform. Keys are unique -> ranks are a
// permutation; rank < PRE elements are the exact sorted top-PRE.
__global__ void __launch_bounds__(256) rank_k(const float* __restrict__ deltas,
                                              const float* __restrict__ ii,
                                              const float* __restrict__ anc) {
    __shared__ u64 tile[256];
    int cnt = g_cand_count; if (cnt > CAP) cnt = CAP;
    int i = blockIdx.x*256 + threadIdx.x;
    if (blockIdx.x*256 >= cnt) return;
    u64 my = (i < cnt) ? g_cand[i] : 0xFFFFFFFFFFFFFFFFull;
    int rank = 0;
    for (int base = 0; base < cnt; base += 256) {
        int j = base + threadIdx.x;
        tile[threadIdx.x] = (j < cnt) ? g_cand[j] : 0ull;   // 0 never counts
        __syncthreads();
        #pragma unroll 8
        for (int k = 0; k < 256; ++k) rank += (tile[k] > my) ? 1 : 0;
        __syncthreads();
    }
    if (i >= cnt || rank >= PRE) return;

    int idx = (int)(0xFFFFFFFFu - (unsigned)(my & 0xFFFFFFFFull));
    float score = __uint_as_float((unsigned)(my >> 32));
    int r = rank;
    int a = idx % 3;
    int p = idx / 3;
    int w = p % WW;
    int h = (p / WW) % HH;
    int s = p / (WW*HH);
    float shx = 4.0f * (float)w, shy = 4.0f * (float)h, shz = 4.0f * (float)s;
    float x1a = __fadd_rn(shx, anc[a*6+0]);
    float y1a = __fadd_rn(shy, anc[a*6+1]);
    float z1a = __fadd_rn(shz, anc[a*6+2]);
    float x2a = __fadd_rn(shx, anc[a*6+3]);
    float y2a = __fadd_rn(shy, anc[a*6+4]);
    float z2a = __fadd_rn(shz, anc[a*6+5]);
    float ww_ = __fadd_rn(__fsub_rn(x2a, x1a), 1.0f);
    float hh_ = __fadd_rn(__fsub_rn(y2a, y1a), 1.0f);
    float dd_ = __fadd_rn(__fsub_rn(z2a, z1a), 1.0f);
    float cx = __fadd_rn(x1a, __fmul_rn(0.5f, ww_));
    float cy = __fadd_rn(y1a, __fmul_rn(0.5f, hh_));
    float cz = __fadd_rn(z1a, __fmul_rn(0.5f, dd_));
    const float* dp = deltas + p;
    float dx = dp[(6*a+0)*KK];
    float dy = dp[(6*a+1)*KK];
    float dz = dp[(6*a+2)*KK];
    float dw = dp[(6*a+3)*KK];
    float dh = dp[(6*a+4)*KK];
    float dd = dp[(6*a+5)*KK];
    float pcx = __fadd_rn(__fmul_rn(dx, ww_), cx);
    float pcy = __fadd_rn(__fmul_rn(dy, hh_), cy);
    float pcz = __fadd_rn(__fmul_rn(dz, dd_), cz);
    float pw = __fmul_rn(expf(dw), ww_);
    float ph = __fmul_rn(expf(dh), hh_);
    float pd = __fmul_rn(expf(dd), dd_);
    float slices = ii[0], height = ii[1], width = ii[2], scale = ii[3];
    float wx = __fsub_rn(width, 1.0f);
    float hy = __fsub_rn(height, 1.0f);
    float sz = __fsub_rn(slices, 1.0f);
    float x1 = fminf(fmaxf(__fsub_rn(pcx, __fmul_rn(0.5f, pw)), 0.0f), wx);
    float y1 = fminf(fmaxf(__fsub_rn(pcy, __fmul_rn(0.5f, ph)), 0.0f), hy);
    float z1 = fminf(fmaxf(__fsub_rn(pcz, __fmul_rn(0.5f, pd)), 0.0f), sz);
    float x2 = fminf(fmaxf(__fsub_rn(__fadd_rn(pcx, __fmul_rn(0.5f, pw)), 1.0f), 0.0f), wx);
    float y2 = fminf(fmaxf(__fsub_rn(__fadd_rn(pcy, __fmul_rn(0.5f, ph)), 1.0f), 0.0f), hy);
    float z2 = fminf(fmaxf(__fsub_rn(__fadd_rn(pcz, __fmul_rn(0.5f, pd)), 1.0f), 0.0f), sz);
    float ss_ = __fadd_rn(__fsub_rn(x2, x1), 1.0f);
    float xc = __fadd_rn(x1, __fmul_rn(ss_, 0.5f));
    float yc = __fadd_rn(y1, __fmul_rn(ss_, 0.5f));
    float zc = __fadd_rn(z1, __fmul_rn(ss_, 0.5f));
    float minsz = __fmul_rn(8.0f, scale);
    int valid = (ss_ >= minsz) && (xc < width) && (yc < height) && (zc < slices);
    float vy = __fadd_rn(__fsub_rn(y2, y1), 1.0f);
    float vz = __fadd_rn(__fsub_rn(z2, z1), 1.0f);
    float vol = __fmul_rn(__fmul_rn(ss_, vy), vz);
    g_bx1[r] = x1; g_by1[r] = y1; g_bz1[r] = z1;
    g_bx2[r] = x2; g_by2[r] = y2; g_bz2[r] = z2;
    g_volv[r] = vol;
    g_valid[r] = valid;
    g_order[r] = idx;
    g_score[r] = score;
}

__global__ void __launch_bounds__(128) mask_k() {
    __shared__ float cx1[64], cy1[64], cz1[64], cx2[64], cy2[64], cz2[64], cv[64];
    int word = blockIdx.x;              // 0..31
    int t = threadIdx.x;                // 128 threads
    if (t < 64) {
        int c = word*64 + t;
        if (c < PRE) {
            cx1[t] = g_bx1[c]; cy1[t] = g_by1[c]; cz1[t] = g_bz1[c];
            cx2[t] = g_bx2[c]; cy2[t] = g_by2[c]; cz2[t] = g_bz2[c];
            cv[t]  = g_volv[c];
        }
    }
    __syncthreads();
    int r = blockIdx.y*blockDim.x + t;
    if (r >= PRE) return;
    float x1 = g_bx1[r], y1 = g_by1[r], z1 = g_bz1[r];
    float x2 = g_bx2[r], y2 = g_by2[r], z2 = g_bz2[r];
    float vr = g_volv[r];
    u64 bits = 0ull;
    #pragma unroll 8
    for (int c = 0; c < 64; ++c) {
        int j = word*64 + c;
        if (j < PRE && j > r) {
            float iw = fmaxf(__fadd_rn(__fsub_rn(fminf(x2, cx2[c]), fmaxf(x1, cx1[c])), 1.0f), 0.0f);
            float ih = fmaxf(__fadd_rn(__fsub_rn(fminf(y2, cy2[c]), fmaxf(y1, cy1[c])), 1.0f), 0.0f);
            float id = fmaxf(__fadd_rn(__fsub_rn(fminf(z2, cz2[c]), fmaxf(z1, cz1[c])), 1.0f), 0.0f);
            float inter = __fmul_rn(__fmul_rn(iw, ih), id);
            float denom = __fsub_rn(__fadd_rn(vr, cv[c]), inter);
            float iou = __fdiv_rn(inter, denom);
            if (iou > NMS_T) bits |= (1ull << c);
        }
    }
    g_mask[(size_t)r*WORDS + word] = bits;
}

__device__ __forceinline__ void fill_one(float* out, int i, int pos) {
    int base = pos*7;
    out[base+0] = 0.0f;
    out[base+1] = g_bx1[i];
    out[base+2] = g_by1[i];
    out[base+3] = g_bz1[i];
    out[base+4] = g_bx2[i];
    out[base+5] = g_by2[i];
    out[base+6] = g_bz2[i];
    out[POST*7 + pos] = g_score[i];          // 2100..2399
    out[POST*8 + pos] = (float)g_order[i];   // 2400..2699
    out[POST*9 + pos] = 1.0f;                // 2700..2999
}

// Merged NMS-reduce + output at 512 threads (reg budget 128/thread — room for
// the 64-register double-buffered NMS in warp 0). Warps 1..15 initialize the
// output buffer concurrently; then a 512-wide scan (4 candidates per thread)
// scatters kept boxes. Resets the candidate counter for the next graph replay.
__global__ void __launch_bounds__(512) final_k(float* __restrict__ out, int out_size) {
    __shared__ int sc[512];
    __shared__ u64 rw[WORDS];
    int t = threadIdx.x;

    if (t < 32) {
        int lane = t;
        u64 rm = 0ull;
        #pragma unroll
        for (int b = 0; b < 64; ++b) {
            int j = lane*64 + b;
            int inval = (j < PRE) ? (g_valid[j] ? 0 : 1) : 1;
            rm |= ((u64)inval) << b;
        }
        const int NCH = (PRE + 15) / 16;    // 125 chunks
        u64 v[16], nx[16];
        #pragma unroll
        for (int b = 0; b < 16; ++b)
            v[b] = g_mask[(size_t)b*WORDS + lane];
        for (int c = 0; c < NCH; ++c) {
            int nbase = (c + 1) * 16;
            #pragma unroll
            for (int b = 0; b < 16; ++b) {
                int row = nbase + b;
                nx[b] = (row < PRE) ? g_mask[(size_t)row*WORDS + lane] : 0ull;
            }
            int w  = (c * 16) >> 6;
            int sh = (c * 16) & 63;
            unsigned acc = 0u;
            if (lane == w) {
                #pragma unroll
                for (int b = 0; b < 16; ++b) {
                    unsigned sup = (unsigned)(rm >> (sh + b)) & 1u;
                    acc |= (sup ^ 1u) << b;
                    rm |= sup ? 0ull : v[b];
                }
            }
            acc = __shfl_sync(0xffffffffu, acc, w);
            #pragma unroll
            for (int b = 0; b < 16; ++b)
                rm |= ((acc >> b) & 1u) ? v[b] : 0ull;
            #pragma unroll
            for (int b = 0; b < 16; ++b) v[b] = nx[b];
        }
        rw[lane] = rm;
    } else {
        // warps 1..15: initialize output defaults in parallel with the reduce
        for (int o = t - 32; o < POST*8; o += 480) if (o < out_size) out[o] = 0.0f;
        for (int o = t - 32; o < POST; o += 480) {
            if (POST*8 + o < out_size) out[POST*8 + o] = -1.0f;
            if (POST*9 + o < out_size) out[POST*9 + o] = 0.0f;
        }
    }
    __syncthreads();

    int kk[4];
    int ksum = 0;
    #pragma unroll
    for (int c = 0; c < 4; ++c) {
        int i = 4*t + c;
        int k = 0;
        if (i < PRE) k = (g_valid[i] && !((rw[i>>6] >> (i & 63)) & 1ull)) ? 1 : 0;
        kk[c] = k;
        ksum += k;
    }
    sc[t] = ksum;
    __syncthreads();
    for (int off = 1; off < 512; off <<= 1) {
        int v = (t >= off) ? sc[t-off] : 0;
        __syncthreads();
        sc[t] += v;
        __syncthreads();
    }
    int pos = sc[t] - ksum;
    if (out_size >= POST*10) {
        #pragma unroll
        for (int c = 0; c < 4; ++c) {
            if (kk[c] && pos < POST) fill_one(out, 4*t + c, pos);
            pos += kk[c];
        }
    }
    if (t == 0) g_cand_count = 0;   // clean state for next graph replay
}

// ---------------- launch ----------------
extern "C" void kernel_launch(void* const* d_in, const int* in_sizes, int n_in,
                              void* d_out, int out_size) {
    const float* scores  = (const float*)d_in[0];
    const float* deltas  = (const float*)d_in[1];
    const float* iminfo  = (const float*)d_in[2];
    const float* anchors = (const float*)d_in[3];
    float* out = (float*)d_out;

    scan_k<<<768, 512>>>((const float4*)scores);       // NN/4 threads exactly
    fb_all_k<<<1, 1024>>>(scores);                     // early-exits normally
    rank_k<<<CAP/256, 256>>>(deltas, iminfo, anchors);
    mask_k<<<dim3(WORDS, (PRE + 127)/128), 128>>>();
    final_k<<<1, 512>>>(out, out_size);
}